// round 6
// baseline (speedup 1.0000x reference)
#include <cuda_runtime.h>
#include <math.h>

#define NN 2048
#define NE 4096
#define DD 128
#define NHEAD 4
#define DHEAD 32
#define NK 819     /* int(0.4*2048) */
#define EK 1638    /* int(0.4*4096) */
#define CAP 64     /* per-node incidence capacity (max random degree ~20) */
#define MAXC (2*CAP)
#define QKV_GRID 148

// ---------------- scratch (device globals; no allocation allowed) ----------------
__device__ float g_nscore[NN];
__device__ float g_escore[NE];
__device__ int   g_nmask[NN];
__device__ int   g_etop[NE];
__device__ int   g_emask[NE];
__device__ int   g_cnt[NN];
__device__ int   g_adj[NN * CAP];
__device__ int   g_epk[NE];          // (src<<16)|dst
__device__ float g_q[NE * DD];
__device__ float g_k[NE * DD];
__device__ float g_v[NE * DD];
__device__ float g_ctx[NE * DD];

__device__ __forceinline__ float wsum(float v) {
    v += __shfl_xor_sync(0xffffffffu, v, 16);
    v += __shfl_xor_sync(0xffffffffu, v, 8);
    v += __shfl_xor_sync(0xffffffffu, v, 4);
    v += __shfl_xor_sync(0xffffffffu, v, 2);
    v += __shfl_xor_sync(0xffffffffu, v, 1);
    return v;
}
__device__ __forceinline__ float wmax(float v) {
    v = fmaxf(v, __shfl_xor_sync(0xffffffffu, v, 16));
    v = fmaxf(v, __shfl_xor_sync(0xffffffffu, v, 8));
    v = fmaxf(v, __shfl_xor_sync(0xffffffffu, v, 4));
    v = fmaxf(v, __shfl_xor_sync(0xffffffffu, v, 2));
    v = fmaxf(v, __shfl_xor_sync(0xffffffffu, v, 1));
    return v;
}
__device__ __forceinline__ int wsumi(int v) {
    v += __shfl_xor_sync(0xffffffffu, v, 16);
    v += __shfl_xor_sync(0xffffffffu, v, 8);
    v += __shfl_xor_sync(0xffffffffu, v, 4);
    v += __shfl_xor_sync(0xffffffffu, v, 2);
    v += __shfl_xor_sync(0xffffffffu, v, 1);
    return v;
}

// ---------------- 1) scores (warp/row) + zero incidence counters ----------------
__global__ __launch_bounds__(256) void k_scores(
    const float* __restrict__ nf, const float* __restrict__ ef,
    const float* __restrict__ wn, const float* __restrict__ we)
{
    int gid = blockIdx.x * 256 + threadIdx.x;
    if (gid < NN) g_cnt[gid] = 0;

    int gw = blockIdx.x * 8 + (threadIdx.x >> 5);
    int lane = threadIdx.x & 31;
    const float* base;
    const float* w;
    if (gw < NN) { base = nf + (size_t)gw * DD; w = wn; }
    else         { base = ef + (size_t)(gw - NN) * DD; w = we; }
    float s = 0.f;
#pragma unroll
    for (int l = 0; l < 4; l++) {
        int d = lane + l * 32;
        s += base[d] * w[d];
    }
    s = wsum(s);
    if (lane == 0) {
        if (gw < NN) g_nscore[gw] = s;
        else         g_escore[gw - NN] = s;
    }
}

// ---------------- 2) exact top-k masks via rank counting ----------------
__global__ __launch_bounds__(256) void k_masks() {
    int gw = blockIdx.x * 8 + (threadIdx.x >> 5);
    int lane = threadIdx.x & 31;
    if (gw < NN) {
        float s = g_nscore[gw];
        int c = 0;
        for (int j = lane; j < NN; j += 32) c += (g_nscore[j] > s);
        c = wsumi(c);
        if (lane == 0) g_nmask[gw] = (c < NK);
    } else {
        int e = gw - NN;
        float s = g_escore[e];
        int c = 0;
        for (int j = lane; j < NE; j += 32) c += (g_escore[j] > s);
        c = wsumi(c);
        if (lane == 0) g_etop[e] = (c < EK);
    }
}

// ---------------- 3) edge mask + incidence lists (fixed capacity) ----------------
__global__ void k_build(const int* __restrict__ ei) {
    int e = blockIdx.x * blockDim.x + threadIdx.x;
    if (e >= NE) return;
    int s = ei[e], d = ei[NE + e];
    g_epk[e] = (s << 16) | d;
    g_emask[e] = (g_etop[e] && g_nmask[s] && g_nmask[d]) ? 1 : 0;
    int p = atomicAdd(&g_cnt[s], 1);
    if (p < CAP) g_adj[s * CAP + p] = e;
    if (d != s) {
        p = atomicAdd(&g_cnt[d], 1);
        if (p < CAP) g_adj[d * CAP + p] = e;
    }
}

// ---------------- 4) fused Q/K/V GEMM: persistent balanced grid, 512 thr, dbl-buffered ----
// 64x128 tile, 512 thr, 2x8 microtile. Jobs: bid<64:K, <128:V, 128..147: Q tiles (stride 20).
// A_kvin[e][k] = k<128: ef[e][k]*mask[e]; k<256: nf[src][k-128]; else nf[dst][k-256]
__global__ __launch_bounds__(512) void k_qkv(
    const float* __restrict__ ef, const float* __restrict__ nf,
    const float* __restrict__ Wq, const float* __restrict__ Wk, const float* __restrict__ Wv,
    const float* __restrict__ bq, const float* __restrict__ bk, const float* __restrict__ bv)
{
    __shared__ __align__(16) float Ast[2][16][68];   // A^T [buf][kk][row]
    __shared__ __align__(16) float Bs[2][16][128];
    __shared__ int   sm_src[64], sm_dst[64];
    __shared__ float sm_m[64];

    int tid = threadIdx.x;
    int bid = blockIdx.x;
    int ty = tid >> 4, tx = tid & 15;   // ty 0..31 (2 rows each), tx 0..15 (8 cols each)

    // job descriptor
    int y, tile0, tstride, tend;
    if (bid < 64)       { y = 1; tile0 = bid;       tstride = 1000; tend = tile0 + 1; }
    else if (bid < 128) { y = 2; tile0 = bid - 64;  tstride = 1000; tend = tile0 + 1; }
    else                { y = 0; tile0 = bid - 128; tstride = 20;   tend = 64; }

    const float* B    = (y == 0) ? Wq : (y == 1) ? Wk : Wv;
    const float* bias = (y == 0) ? bq : (y == 1) ? bk : bv;
    float* C          = (y == 0) ? g_q : (y == 1) ? g_k : g_v;
    int kdim          = (y == 0) ? 128 : 384;
    int T             = kdim >> 4;

    for (int tile = tile0; tile < tend; tile += tstride) {
        int rb = tile * 64;
        __syncthreads();   // protect meta arrays across jobs
        if (tid < 64) {
            int e = rb + tid;
            int pk = g_epk[e];
            sm_src[tid] = pk >> 16;
            sm_dst[tid] = pk & 0xffff;
            sm_m[tid] = g_emask[e] ? 1.f : 0.f;
        }
        __syncthreads();

        float acc[2][8];
#pragma unroll
        for (int i = 0; i < 2; i++)
#pragma unroll
            for (int j = 0; j < 8; j++) acc[i][j] = 0.f;

        float aReg[2];
        float4 bReg;

        auto loadT = [&](int t) {
            int k0 = t * 16;
#pragma unroll
            for (int l = 0; l < 2; l++) {
                int idx = tid + l * 512;
                int kk = idx & 15, r = idx >> 4;
                int k = k0 + kk;
                float v;
                if (k < 128)       v = ef[(rb + r) * DD + k] * sm_m[r];
                else if (k < 256)  v = nf[sm_src[r] * DD + (k - 128)];
                else               v = nf[sm_dst[r] * DD + (k - 256)];
                aReg[l] = v;
            }
            bReg = ((const float4*)(B + (size_t)k0 * DD))[tid];
        };
        auto storeT = [&](int buf) {
#pragma unroll
            for (int l = 0; l < 2; l++) {
                int idx = tid + l * 512;
                Ast[buf][idx & 15][idx >> 4] = aReg[l];
            }
            ((float4*)&Bs[buf][0][0])[tid] = bReg;
        };

        loadT(0);
        storeT(0);
        __syncthreads();

        for (int t = 0; t < T; t++) {
            int buf = t & 1;
            if (t + 1 < T) loadT(t + 1);   // global latency overlapped with compute
#pragma unroll
            for (int kk = 0; kk < 16; kk++) {
                float a[2], b[8];
                *(float2*)&a[0] = *(const float2*)&Ast[buf][kk][ty * 2];
                *(float4*)&b[0] = *(const float4*)&Bs[buf][kk][tx * 8];
                *(float4*)&b[4] = *(const float4*)&Bs[buf][kk][tx * 8 + 4];
#pragma unroll
                for (int i = 0; i < 2; i++)
#pragma unroll
                    for (int j = 0; j < 8; j++) acc[i][j] += a[i] * b[j];
            }
            __syncthreads();
            if (t + 1 < T) {
                storeT(buf ^ 1);
                __syncthreads();
            }
        }

#pragma unroll
        for (int i = 0; i < 2; i++) {
            int row = rb + ty * 2 + i;
            float4 o0, o1;
            o0.x = acc[i][0] + bias[tx * 8 + 0];
            o0.y = acc[i][1] + bias[tx * 8 + 1];
            o0.z = acc[i][2] + bias[tx * 8 + 2];
            o0.w = acc[i][3] + bias[tx * 8 + 3];
            o1.x = acc[i][4] + bias[tx * 8 + 4];
            o1.y = acc[i][5] + bias[tx * 8 + 5];
            o1.z = acc[i][6] + bias[tx * 8 + 6];
            o1.w = acc[i][7] + bias[tx * 8 + 7];
            *(float4*)&C[(size_t)row * DD + tx * 8] = o0;
            *(float4*)&C[(size_t)row * DD + tx * 8 + 4] = o1;
        }
    }
}

// ---------------- 5) sparse edge attention (block/edge, warp/head) ----------------
__global__ __launch_bounds__(128) void k_attn() {
    __shared__ int cand[MAXC];
    __shared__ int s_nc;
    __shared__ float sc[NHEAD][MAXC];
    int e = blockIdx.x;
    int tid = threadIdx.x;
    int pk = g_epk[e];
    int qs = pk >> 16, qd = pk & 0xffff;
    if (tid == 0) {
        int n = 0;
        int cs = min(g_cnt[qs], CAP);
        for (int p = 0; p < cs; p++) cand[n++] = g_adj[qs * CAP + p];
        if (qd != qs) {
            int cd = min(g_cnt[qd], CAP);
            for (int p = 0; p < cd; p++) {
                int f = g_adj[qd * CAP + p];
                int fp = g_epk[f];
                if ((fp >> 16) != qs && (fp & 0xffff) != qs) cand[n++] = f;
            }
        }
        s_nc = n;
    }
    __syncthreads();
    int nc = s_nc;
    int h = tid >> 5, lane = tid & 31;
    float qv = g_q[(size_t)e * DD + h * DHEAD + lane];
    const float scale = 0.17677669529663687f; // 1/sqrt(32)
    for (int c = 0; c < nc; c++) {
        int f = cand[c];
        float t = qv * g_k[(size_t)f * DD + h * DHEAD + lane];
        t = wsum(t);
        if (lane == 0) sc[h][c] = t * scale;
    }
    __syncwarp();
    float m = -1e30f;
    for (int c = lane; c < nc; c += 32) m = fmaxf(m, sc[h][c]);
    m = wmax(m);
    float l = 0.f;
    for (int c = lane; c < nc; c += 32) {
        float p = expf(sc[h][c] - m);
        sc[h][c] = p;
        l += p;
    }
    l = wsum(l);
    __syncwarp();
    float acc = 0.f;
    for (int c = 0; c < nc; c++)
        acc += sc[h][c] * g_v[(size_t)cand[c] * DD + h * DHEAD + lane];
    g_ctx[(size_t)e * DD + h * DHEAD + lane] = acc / l;
}

// ---------------- 6) tail megakernel: 32x128 tile, 256 thr, 2x8 microtile ----------------
// upd = ctx@Wo + bo + wef ; hid = gelu(upd@W1 + b1) ; out = hid@W2 + b2
__global__ __launch_bounds__(256) void k_tail(
    const float* __restrict__ ef,
    const float* __restrict__ Wo, const float* __restrict__ bo,
    const float* __restrict__ W1, const float* __restrict__ b1,
    const float* __restrict__ W2, const float* __restrict__ b2,
    float* __restrict__ out)
{
    __shared__ __align__(16) float Ast[16][36];   // ctx^T tile [kk][row(32)], pad 36
    __shared__ __align__(16) float Bs[16][128];
    __shared__ __align__(16) float Us[32][132];   // upd [row][col]
    __shared__ float sm_m[32];

    int tid = threadIdx.x;
    int rb = blockIdx.x * 32;
    if (tid < 32) sm_m[tid] = g_emask[rb + tid] ? 1.f : 0.f;

    int ty = tid >> 4, tx = tid & 15;   // ty 0..15 (2 rows each), tx 0..15 (8 cols)
    float acc[2][8];
#pragma unroll
    for (int i = 0; i < 2; i++)
#pragma unroll
        for (int j = 0; j < 8; j++) acc[i][j] = 0.f;

    // ---- stage 1: upd = ctx @ Wo ----
    for (int k0 = 0; k0 < 128; k0 += 16) {
#pragma unroll
        for (int l = 0; l < 2; l++) {
            int idx = tid + l * 256;
            int kk = idx & 15, r = idx >> 4;
            Ast[kk][r] = g_ctx[(size_t)(rb + r) * DD + k0 + kk];
        }
        {
            const float4* src = (const float4*)(Wo + (size_t)k0 * DD);
            float4* dst = (float4*)&Bs[0][0];
            dst[tid] = src[tid];
            dst[tid + 256] = src[tid + 256];
        }
        __syncthreads();
#pragma unroll
        for (int kk = 0; kk < 16; kk++) {
            float a[2], b[8];
            *(float2*)&a[0] = *(const float2*)&Ast[kk][ty * 2];
            *(float4*)&b[0] = *(const float4*)&Bs[kk][tx * 8];
            *(float4*)&b[4] = *(const float4*)&Bs[kk][tx * 8 + 4];
#pragma unroll
            for (int i = 0; i < 2; i++)
#pragma unroll
                for (int j = 0; j < 8; j++) acc[i][j] += a[i] * b[j];
        }
        __syncthreads();
    }
    // epilogue 1: + bo + residual(wef) -> Us, reset acc
#pragma unroll
    for (int i = 0; i < 2; i++) {
        int r = ty * 2 + i;
        int e = rb + r;
#pragma unroll
        for (int j = 0; j < 8; j++) {
            int col = tx * 8 + j;
            Us[r][col] = acc[i][j] + bo[col] + ef[(size_t)e * DD + col] * sm_m[r];
            acc[i][j] = 0.f;
        }
    }
    __syncthreads();

    // ---- stage 2: hid = gelu(upd @ W1 + b1) ----
    for (int k0 = 0; k0 < 128; k0 += 16) {
        {
            const float4* src = (const float4*)(W1 + (size_t)k0 * DD);
            float4* dst = (float4*)&Bs[0][0];
            dst[tid] = src[tid];
            dst[tid + 256] = src[tid + 256];
        }
        __syncthreads();
#pragma unroll
        for (int kk = 0; kk < 16; kk++) {
            float b[8];
            *(float4*)&b[0] = *(const float4*)&Bs[kk][tx * 8];
            *(float4*)&b[4] = *(const float4*)&Bs[kk][tx * 8 + 4];
#pragma unroll
            for (int i = 0; i < 2; i++) {
                float a = Us[ty * 2 + i][k0 + kk];
#pragma unroll
                for (int j = 0; j < 8; j++) acc[i][j] += a * b[j];
            }
        }
        __syncthreads();
    }
    // gelu (tanh approx, matches jax.nn.gelu default)
#pragma unroll
    for (int i = 0; i < 2; i++)
#pragma unroll
        for (int j = 0; j < 8; j++) {
            int col = tx * 8 + j;
            float x = acc[i][j] + b1[col];
            acc[i][j] = 0.5f * x * (1.f + tanhf(0.7978845608028654f * (x + 0.044715f * x * x * x)));
        }

    // ---- stage 3: out = hid @ W2 + b2 (register partials + shfl reduce over tx) ----
    float4 w4[8];
#pragma unroll
    for (int j = 0; j < 8; j++) w4[j] = *(const float4*)&W2[(tx * 8 + j) * 4];

#pragma unroll
    for (int i = 0; i < 2; i++) {
        float p0 = 0.f, p1 = 0.f, p2 = 0.f, p3 = 0.f;
#pragma unroll
        for (int j = 0; j < 8; j++) {
            float h = acc[i][j];
            p0 += h * w4[j].x;
            p1 += h * w4[j].y;
            p2 += h * w4[j].z;
            p3 += h * w4[j].w;
        }
#pragma unroll
        for (int off = 1; off < 16; off <<= 1) {
            p0 += __shfl_xor_sync(0xffffffffu, p0, off);
            p1 += __shfl_xor_sync(0xffffffffu, p1, off);
            p2 += __shfl_xor_sync(0xffffffffu, p2, off);
            p3 += __shfl_xor_sync(0xffffffffu, p3, off);
        }
        if (tx == 0) {
            int row = rb + ty * 2 + i;
            out[row * 4 + 0] = p0 + b2[0];
            out[row * 4 + 1] = p1 + b2[1];
            out[row * 4 + 2] = p2 + b2[2];
            out[row * 4 + 3] = p3 + b2[3];
        }
    }
}

// ---------------- launch ----------------
extern "C" void kernel_launch(void* const* d_in, const int* in_sizes, int n_in,
                              void* d_out, int out_size) {
    const float* nf = (const float*)d_in[0];
    const float* ef = (const float*)d_in[1];
    const int*   ei = (const int*)d_in[2];
    const float* wn = (const float*)d_in[3];
    const float* we = (const float*)d_in[4];
    const float* Wq = (const float*)d_in[5];
    const float* bq = (const float*)d_in[6];
    const float* Wk = (const float*)d_in[7];
    const float* bk = (const float*)d_in[8];
    const float* Wv = (const float*)d_in[9];
    const float* bv = (const float*)d_in[10];
    const float* Wo = (const float*)d_in[11];
    const float* bo = (const float*)d_in[12];
    const float* W1 = (const float*)d_in[13];
    const float* b1 = (const float*)d_in[14];
    const float* W2 = (const float*)d_in[15];
    const float* b2 = (const float*)d_in[16];
    float* out = (float*)d_out;

    k_scores<<<768, 256>>>(nf, ef, wn, we);
    k_masks<<<768, 256>>>();
    k_build<<<16, 256>>>(ei);
    k_qkv<<<QKV_GRID, 512>>>(ef, nf, Wq, Wk, Wv, bq, bk, bv);
    k_attn<<<4096, 128>>>();
    k_tail<<<128, 256>>>(ef, Wo, bo, W1, b1, W2, b2, out);
}

// round 8
// speedup vs baseline: 1.8400x; 1.8400x over previous
#include <cuda_runtime.h>
#include <math.h>

#define NN 2048
#define NE 4096
#define DD 128
#define NHEAD 4
#define DHEAD 32
#define NK 819     /* int(0.4*2048) */
#define EK 1638    /* int(0.4*4096) */
#define CAP 64     /* per-node incidence capacity (max random degree ~20) */
#define MAXC (2*CAP)

// ---------------- scratch (device globals; no allocation allowed) ----------------
__device__ float g_nscore[NN];
__device__ float g_escore[NE];
__device__ int   g_nmask[NN];
__device__ int   g_etop[NE];
__device__ int   g_emask[NE];
__device__ int   g_cnt[NN];
__device__ int   g_adj[NN * CAP];
__device__ int   g_epk[NE];          // (src<<16)|dst
__device__ float g_nk2[NN * DD];     // nf @ Wk[128:256]
__device__ float g_nk3[NN * DD];     // nf @ Wk[256:384]
__device__ float g_nv2[NN * DD];     // nf @ Wv[128:256]
__device__ float g_nv3[NN * DD];     // nf @ Wv[256:384]
__device__ float g_q[NE * DD];
__device__ float g_k[NE * DD];
__device__ float g_v[NE * DD];
__device__ float g_ctx[NE * DD];

__device__ __forceinline__ float wsum(float v) {
    v += __shfl_xor_sync(0xffffffffu, v, 16);
    v += __shfl_xor_sync(0xffffffffu, v, 8);
    v += __shfl_xor_sync(0xffffffffu, v, 4);
    v += __shfl_xor_sync(0xffffffffu, v, 2);
    v += __shfl_xor_sync(0xffffffffu, v, 1);
    return v;
}
__device__ __forceinline__ float wmax(float v) {
    v = fmaxf(v, __shfl_xor_sync(0xffffffffu, v, 16));
    v = fmaxf(v, __shfl_xor_sync(0xffffffffu, v, 8));
    v = fmaxf(v, __shfl_xor_sync(0xffffffffu, v, 4));
    v = fmaxf(v, __shfl_xor_sync(0xffffffffu, v, 2));
    v = fmaxf(v, __shfl_xor_sync(0xffffffffu, v, 1));
    return v;
}
__device__ __forceinline__ int wsumi(int v) {
    v += __shfl_xor_sync(0xffffffffu, v, 16);
    v += __shfl_xor_sync(0xffffffffu, v, 8);
    v += __shfl_xor_sync(0xffffffffu, v, 4);
    v += __shfl_xor_sync(0xffffffffu, v, 2);
    v += __shfl_xor_sync(0xffffffffu, v, 1);
    return v;
}

// ---------------- 1) scores (warp/row) + zero incidence counters ----------------
__global__ __launch_bounds__(256) void k_scores(
    const float* __restrict__ nf, const float* __restrict__ ef,
    const float* __restrict__ wn, const float* __restrict__ we)
{
    int gid = blockIdx.x * 256 + threadIdx.x;
    if (gid < NN) g_cnt[gid] = 0;

    int gw = blockIdx.x * 8 + (threadIdx.x >> 5);
    int lane = threadIdx.x & 31;
    const float* base;
    const float* w;
    if (gw < NN) { base = nf + (size_t)gw * DD; w = wn; }
    else         { base = ef + (size_t)(gw - NN) * DD; w = we; }
    float s = 0.f;
#pragma unroll
    for (int l = 0; l < 4; l++) {
        int d = lane + l * 32;
        s += base[d] * w[d];
    }
    s = wsum(s);
    if (lane == 0) {
        if (gw < NN) g_nscore[gw] = s;
        else         g_escore[gw - NN] = s;
    }
}

// ---------------- 2) exact top-k masks via rank counting ----------------
__global__ __launch_bounds__(256) void k_masks() {
    int gw = blockIdx.x * 8 + (threadIdx.x >> 5);
    int lane = threadIdx.x & 31;
    if (gw < NN) {
        float s = g_nscore[gw];
        int c = 0;
        for (int j = lane; j < NN; j += 32) c += (g_nscore[j] > s);
        c = wsumi(c);
        if (lane == 0) g_nmask[gw] = (c < NK);
    } else {
        int e = gw - NN;
        float s = g_escore[e];
        int c = 0;
        for (int j = lane; j < NE; j += 32) c += (g_escore[j] > s);
        c = wsumi(c);
        if (lane == 0) g_etop[e] = (c < EK);
    }
}

// ---------------- 3) edge mask + incidence lists (fixed capacity) ----------------
__global__ void k_build(const int* __restrict__ ei) {
    int e = blockIdx.x * blockDim.x + threadIdx.x;
    if (e >= NE) return;
    int s = ei[e], d = ei[NE + e];
    g_epk[e] = (s << 16) | d;
    g_emask[e] = (g_etop[e] && g_nmask[s] && g_nmask[d]) ? 1 : 0;
    int p = atomicAdd(&g_cnt[s], 1);
    if (p < CAP) g_adj[s * CAP + p] = e;
    if (d != s) {
        p = atomicAdd(&g_cnt[d], 1);
        if (p < CAP) g_adj[d * CAP + p] = e;
    }
}

// ---------------- 4) node projections: [2048x128] @ [128x128] x4 ----------------
// y: 0 -> nf@Wk[128:256] (g_nk2), 1 -> nf@Wk[256:384] (g_nk3),
//    2 -> nf@Wv[128:256] (g_nv2), 3 -> nf@Wv[256:384] (g_nv3)
// 64x128 tile, 256 thr, 4x8 microtile, double-buffered.
__global__ __launch_bounds__(256) void k_nodeproj(
    const float* __restrict__ nf,
    const float* __restrict__ Wk, const float* __restrict__ Wv)
{
    __shared__ __align__(16) float Ast[2][16][68];
    __shared__ __align__(16) float Bs[2][16][128];

    int tid = threadIdx.x;
    int rb = blockIdx.x * 64;
    int y = blockIdx.y;
    const float* B = (y == 0) ? Wk + 128 * DD : (y == 1) ? Wk + 256 * DD
                   : (y == 2) ? Wv + 128 * DD : Wv + 256 * DD;
    float* C = (y == 0) ? g_nk2 : (y == 1) ? g_nk3 : (y == 2) ? g_nv2 : g_nv3;

    int ty = tid >> 4, tx = tid & 15;   // ty 0..15 (4 rows), tx 0..15 (8 cols)
    float acc[4][8];
#pragma unroll
    for (int i = 0; i < 4; i++)
#pragma unroll
        for (int j = 0; j < 8; j++) acc[i][j] = 0.f;

    float aReg[4];
    float4 bReg[2];
    auto loadT = [&](int t) {
        int k0 = t * 16;
#pragma unroll
        for (int l = 0; l < 4; l++) {
            int idx = tid + l * 256;
            int kk = idx & 15, r = idx >> 4;
            aReg[l] = nf[(size_t)(rb + r) * DD + k0 + kk];
        }
        const float4* src = (const float4*)(B + (size_t)k0 * DD);
        bReg[0] = src[tid];
        bReg[1] = src[tid + 256];
    };
    auto storeT = [&](int buf) {
#pragma unroll
        for (int l = 0; l < 4; l++) {
            int idx = tid + l * 256;
            Ast[buf][idx & 15][idx >> 4] = aReg[l];
        }
        float4* dst = (float4*)&Bs[buf][0][0];
        dst[tid] = bReg[0];
        dst[tid + 256] = bReg[1];
    };

    loadT(0);
    storeT(0);
    __syncthreads();

    const int T = 8;
    for (int t = 0; t < T; t++) {
        int buf = t & 1;
        if (t + 1 < T) loadT(t + 1);
#pragma unroll
        for (int kk = 0; kk < 16; kk++) {
            float a[4], b[8];
            *(float4*)&a[0] = *(const float4*)&Ast[buf][kk][ty * 4];
            *(float4*)&b[0] = *(const float4*)&Bs[buf][kk][tx * 8];
            *(float4*)&b[4] = *(const float4*)&Bs[buf][kk][tx * 8 + 4];
#pragma unroll
            for (int i = 0; i < 4; i++)
#pragma unroll
                for (int j = 0; j < 8; j++) acc[i][j] += a[i] * b[j];
        }
        __syncthreads();
        if (t + 1 < T) {
            storeT(buf ^ 1);
            __syncthreads();
        }
    }

#pragma unroll
    for (int i = 0; i < 4; i++) {
        int row = rb + ty * 4 + i;
        float4 o0 = {acc[i][0], acc[i][1], acc[i][2], acc[i][3]};
        float4 o1 = {acc[i][4], acc[i][5], acc[i][6], acc[i][7]};
        *(float4*)&C[(size_t)row * DD + tx * 8] = o0;
        *(float4*)&C[(size_t)row * DD + tx * 8 + 4] = o1;
    }
}

// ---------------- 5) assemble Q/K/V + sparse wef corrections ----------------
// K[e] = nk2[src] + nk3[dst] + bk (+ ef[e]@Wk[0:128] if masked); V likewise.
// Q[e] = bq (+ ef[e]@Wq if masked). Block per edge; mask is block-uniform
// (branch condition depends only on blockIdx.x, so the __syncthreads inside is safe).
__global__ __launch_bounds__(128) void k_kvq(
    const float* __restrict__ ef,
    const float* __restrict__ Wq, const float* __restrict__ Wk, const float* __restrict__ Wv,
    const float* __restrict__ bq, const float* __restrict__ bk, const float* __restrict__ bv)
{
    __shared__ float efs[DD];
    int e = blockIdx.x;
    int c = threadIdx.x;
    int pk = g_epk[e];
    int s = pk >> 16, d = pk & 0xffff;

    float kacc = g_nk2[(size_t)s * DD + c] + g_nk3[(size_t)d * DD + c] + bk[c];
    float vacc = g_nv2[(size_t)s * DD + c] + g_nv3[(size_t)d * DD + c] + bv[c];
    float qacc = bq[c];

    if (g_emask[e]) {                       // block-uniform branch
        efs[c] = ef[(size_t)e * DD + c];
        __syncthreads();
#pragma unroll 4
        for (int k = 0; k < DD; k++) {
            float a = efs[k];
            qacc += a * Wq[k * DD + c];
            kacc += a * Wk[k * DD + c];
            vacc += a * Wv[k * DD + c];
        }
    }
    g_q[(size_t)e * DD + c] = qacc;
    g_k[(size_t)e * DD + c] = kacc;
    g_v[(size_t)e * DD + c] = vacc;
}

// ---------------- 6) sparse edge attention (block/edge, warp/head) ----------------
__global__ __launch_bounds__(128) void k_attn() {
    __shared__ int cand[MAXC];
    __shared__ int s_nc;
    __shared__ float sc[NHEAD][MAXC];
    int e = blockIdx.x;
    int tid = threadIdx.x;
    int pk = g_epk[e];
    int qs = pk >> 16, qd = pk & 0xffff;
    if (tid == 0) {
        int n = 0;
        int cs = min(g_cnt[qs], CAP);
        for (int p = 0; p < cs; p++) cand[n++] = g_adj[qs * CAP + p];
        if (qd != qs) {
            int cd = min(g_cnt[qd], CAP);
            for (int p = 0; p < cd; p++) {
                int f = g_adj[qd * CAP + p];
                int fp = g_epk[f];
                if ((fp >> 16) != qs && (fp & 0xffff) != qs) cand[n++] = f;
            }
        }
        s_nc = n;
    }
    __syncthreads();
    int nc = s_nc;
    int h = tid >> 5, lane = tid & 31;
    float qv = g_q[(size_t)e * DD + h * DHEAD + lane];
    const float scale = 0.17677669529663687f; // 1/sqrt(32)
    for (int c = 0; c < nc; c++) {
        int f = cand[c];
        float t = qv * g_k[(size_t)f * DD + h * DHEAD + lane];
        t = wsum(t);
        if (lane == 0) sc[h][c] = t * scale;
    }
    __syncwarp();
    float m = -1e30f;
    for (int c = lane; c < nc; c += 32) m = fmaxf(m, sc[h][c]);
    m = wmax(m);
    float l = 0.f;
    for (int c = lane; c < nc; c += 32) {
        float p = expf(sc[h][c] - m);
        sc[h][c] = p;
        l += p;
    }
    l = wsum(l);
    __syncwarp();
    float acc = 0.f;
    for (int c = 0; c < nc; c++)
        acc += sc[h][c] * g_v[(size_t)cand[c] * DD + h * DHEAD + lane];
    g_ctx[(size_t)e * DD + h * DHEAD + lane] = acc / l;
}

// ---------------- 7) tail megakernel: 32x128 tile, 256 thr, 2x8 microtile ----------------
// upd = ctx@Wo + bo + wef ; hid = gelu(upd@W1 + b1) ; out = hid@W2 + b2
__global__ __launch_bounds__(256) void k_tail(
    const float* __restrict__ ef,
    const float* __restrict__ Wo, const float* __restrict__ bo,
    const float* __restrict__ W1, const float* __restrict__ b1,
    const float* __restrict__ W2, const float* __restrict__ b2,
    float* __restrict__ out)
{
    __shared__ __align__(16) float Ast[16][36];   // ctx^T tile [kk][row(32)], pad 36
    __shared__ __align__(16) float Bs[16][128];
    __shared__ __align__(16) float Us[32][132];   // upd [row][col]
    __shared__ float sm_m[32];

    int tid = threadIdx.x;
    int rb = blockIdx.x * 32;
    if (tid < 32) sm_m[tid] = g_emask[rb + tid] ? 1.f : 0.f;

    int ty = tid >> 4, tx = tid & 15;   // ty 0..15 (2 rows each), tx 0..15 (8 cols)
    float acc[2][8];
#pragma unroll
    for (int i = 0; i < 2; i++)
#pragma unroll
        for (int j = 0; j < 8; j++) acc[i][j] = 0.f;

    // ---- stage 1: upd = ctx @ Wo ----
    for (int k0 = 0; k0 < 128; k0 += 16) {
#pragma unroll
        for (int l = 0; l < 2; l++) {
            int idx = tid + l * 256;
            int kk = idx & 15, r = idx >> 4;
            Ast[kk][r] = g_ctx[(size_t)(rb + r) * DD + k0 + kk];
        }
        {
            const float4* src = (const float4*)(Wo + (size_t)k0 * DD);
            float4* dst = (float4*)&Bs[0][0];
            dst[tid] = src[tid];
            dst[tid + 256] = src[tid + 256];
        }
        __syncthreads();
#pragma unroll
        for (int kk = 0; kk < 16; kk++) {
            float a[2], b[8];
            *(float2*)&a[0] = *(const float2*)&Ast[kk][ty * 2];
            *(float4*)&b[0] = *(const float4*)&Bs[kk][tx * 8];
            *(float4*)&b[4] = *(const float4*)&Bs[kk][tx * 8 + 4];
#pragma unroll
            for (int i = 0; i < 2; i++)
#pragma unroll
                for (int j = 0; j < 8; j++) acc[i][j] += a[i] * b[j];
        }
        __syncthreads();
    }
    // epilogue 1: + bo + residual(wef) -> Us, reset acc
#pragma unroll
    for (int i = 0; i < 2; i++) {
        int r = ty * 2 + i;
        int e = rb + r;
#pragma unroll
        for (int j = 0; j < 8; j++) {
            int col = tx * 8 + j;
            Us[r][col] = acc[i][j] + bo[col] + ef[(size_t)e * DD + col] * sm_m[r];
            acc[i][j] = 0.f;
        }
    }
    __syncthreads();

    // ---- stage 2: hid = gelu(upd @ W1 + b1) ----
    for (int k0 = 0; k0 < 128; k0 += 16) {
        {
            const float4* src = (const float4*)(W1 + (size_t)k0 * DD);
            float4* dst = (float4*)&Bs[0][0];
            dst[tid] = src[tid];
            dst[tid + 256] = src[tid + 256];
        }
        __syncthreads();
#pragma unroll
        for (int kk = 0; kk < 16; kk++) {
            float b[8];
            *(float4*)&b[0] = *(const float4*)&Bs[kk][tx * 8];
            *(float4*)&b[4] = *(const float4*)&Bs[kk][tx * 8 + 4];
#pragma unroll
            for (int i = 0; i < 2; i++) {
                float a = Us[ty * 2 + i][k0 + kk];
#pragma unroll
                for (int j = 0; j < 8; j++) acc[i][j] += a * b[j];
            }
        }
        __syncthreads();
    }
    // gelu (tanh approx, matches jax.nn.gelu default)
#pragma unroll
    for (int i = 0; i < 2; i++)
#pragma unroll
        for (int j = 0; j < 8; j++) {
            int col = tx * 8 + j;
            float x = acc[i][j] + b1[col];
            acc[i][j] = 0.5f * x * (1.f + tanhf(0.7978845608028654f * (x + 0.044715f * x * x * x)));
        }

    // ---- stage 3: out = hid @ W2 + b2 (register partials + shfl reduce over tx) ----
    float4 w4[8];
#pragma unroll
    for (int j = 0; j < 8; j++) w4[j] = *(const float4*)&W2[(tx * 8 + j) * 4];

#pragma unroll
    for (int i = 0; i < 2; i++) {
        float p0 = 0.f, p1 = 0.f, p2 = 0.f, p3 = 0.f;
#pragma unroll
        for (int j = 0; j < 8; j++) {
            float h = acc[i][j];
            p0 += h * w4[j].x;
            p1 += h * w4[j].y;
            p2 += h * w4[j].z;
            p3 += h * w4[j].w;
        }
#pragma unroll
        for (int off = 1; off < 16; off <<= 1) {
            p0 += __shfl_xor_sync(0xffffffffu, p0, off);
            p1 += __shfl_xor_sync(0xffffffffu, p1, off);
            p2 += __shfl_xor_sync(0xffffffffu, p2, off);
            p3 += __shfl_xor_sync(0xffffffffu, p3, off);
        }
        if (tx == 0) {
            int row = rb + ty * 2 + i;
            out[row * 4 + 0] = p0 + b2[0];
            out[row * 4 + 1] = p1 + b2[1];
            out[row * 4 + 2] = p2 + b2[2];
            out[row * 4 + 3] = p3 + b2[3];
        }
    }
}

// ---------------- launch ----------------
extern "C" void kernel_launch(void* const* d_in, const int* in_sizes, int n_in,
                              void* d_out, int out_size) {
    const float* nf = (const float*)d_in[0];
    const float* ef = (const float*)d_in[1];
    const int*   ei = (const int*)d_in[2];
    const float* wn = (const float*)d_in[3];
    const float* we = (const float*)d_in[4];
    const float* Wq = (const float*)d_in[5];
    const float* bq = (const float*)d_in[6];
    const float* Wk = (const float*)d_in[7];
    const float* bk = (const float*)d_in[8];
    const float* Wv = (const float*)d_in[9];
    const float* bv = (const float*)d_in[10];
    const float* Wo = (const float*)d_in[11];
    const float* bo = (const float*)d_in[12];
    const float* W1 = (const float*)d_in[13];
    const float* b1 = (const float*)d_in[14];
    const float* W2 = (const float*)d_in[15];
    const float* b2 = (const float*)d_in[16];
    float* out = (float*)d_out;

    k_scores<<<768, 256>>>(nf, ef, wn, we);
    k_masks<<<768, 256>>>();
    k_build<<<16, 256>>>(ei);
    k_nodeproj<<<dim3(32, 4), 256>>>(nf, Wk, Wv);
    k_kvq<<<4096, 128>>>(ef, Wq, Wk, Wv, bq, bk, bv);
    k_attn<<<4096, 128>>>();
    k_tail<<<128, 256>>>(ef, Wo, bo, W1, b1, W2, b2, out);
}